// round 7
// baseline (speedup 1.0000x reference)
#include <cuda_runtime.h>
#include <cuda_bf16.h>
#include <mma.h>
#include <cstdint>

using namespace nvcuda;

#define NN 8192
#define DD 512
#define NC 100
#define KSPLIT 16

// ---------------- scratch ---------------------------------------------------
__device__ __nv_bfloat16 g_z16[2][NN * DD];         // bf16 row-major copies
__device__ float  g_colsum[2][DD];
__device__ float  g_colsumsq[2][DD];
__device__ float  g_clsraw[2][NC * DD];
__device__ float  g_gpart[2 * KSPLIT * 10 * 16384];
__device__ int    g_cnt[NC];
__device__ int    g_start[NC];
__device__ int    g_order[NN];
__device__ double g_acc[2];

__device__ __forceinline__ uint32_t smem_u32(const void* p) {
    uint32_t a;
    asm("{ .reg .u64 t; cvta.to.shared.u64 t, %1; cvt.u32.u64 %0, t; }" : "=r"(a) : "l"(p));
    return a;
}
__device__ __forceinline__ void cp16(uint32_t dst, const void* src) {
    asm volatile("cp.async.cg.shared.global [%0], [%1], 16;" :: "r"(dst), "l"(src) : "memory");
}

// ---------------- K0: fused prep (zero, detect, hist, scan, order) ---------
// single block, 1024 threads
__global__ void __launch_bounds__(1024) k_prep(const int* __restrict__ labels_raw) {
    __shared__ int h[NC];
    __shared__ int pos[NC];
    __shared__ int s_is64;
    int t = threadIdx.x;

    // zero small accumulators
    for (int i = t; i < 2 * DD; i += 1024) {
        g_colsum[0][i & (DD - 1)] = 0.0f;   // covers both via two passes below
    }
    // explicit zeroing (simpler, exact)
    for (int i = t; i < DD; i += 1024) {
        g_colsum[0][i] = 0.0f; g_colsum[1][i] = 0.0f;
        g_colsumsq[0][i] = 0.0f; g_colsumsq[1][i] = 0.0f;
    }
    if (t < NC) h[t] = 0;
    if (t < 2) g_acc[t] = 0.0;
    if (t == 0) {
        int all0 = 1;
        for (int j = 1; j < 128; j += 2) if (labels_raw[j] != 0) { all0 = 0; break; }
        s_is64 = all0;
    }
    __syncthreads();
    const int is64 = s_is64;

    // histogram (smem)
#pragma unroll
    for (int i = t; i < NN; i += 1024) {
        int l = is64 ? labels_raw[2 * i] : labels_raw[i];
        atomicAdd(&h[l], 1);
    }
    __syncthreads();
    // scan (serial, 100 elements)
    if (t == 0) {
        int acc = 0;
        for (int k = 0; k < NC; k++) {
            g_cnt[k] = h[k];
            g_start[k] = acc;
            pos[k] = acc;
            acc += h[k];
        }
    }
    __syncthreads();
    // scatter order (smem atomics)
#pragma unroll
    for (int i = t; i < NN; i += 1024) {
        int l = is64 ? labels_raw[2 * i] : labels_raw[i];
        int idx = atomicAdd(&pos[l], 1);
        g_order[idx] = i;
    }
}

// ---------------- K1: fp32 -> bf16 row-major + column stats ----------------
// grid (4 col-tiles, 32 row-tiles, 2), block 256
__global__ void k_convert(const float* __restrict__ za,
                          const float* __restrict__ zb) {
    int which = blockIdx.z;
    const float* z = which ? zb : za;
    __nv_bfloat16* o = g_z16[which];

    __shared__ float ssum[256], ssq[256];
    int t = threadIdx.x;
    int col = t & 127;
    int half = t >> 7;
    int c0 = blockIdx.x * 128;
    int r0 = blockIdx.y * 256;

    float s = 0.0f, sq = 0.0f;
#pragma unroll 4
    for (int r = half; r < 256; r += 2) {
        int idx = (r0 + r) * DD + c0 + col;
        float v = z[idx];
        o[idx] = __float2bfloat16(v);
        s += v; sq += v * v;
    }
    ssum[t] = s; ssq[t] = sq;
    __syncthreads();
    if (half == 0) {
        atomicAdd(&g_colsum[which][c0 + col], ssum[t] + ssum[t + 128]);
        atomicAdd(&g_colsumsq[which][c0 + col], ssq[t] + ssq[t + 128]);
    }
}

// ---------------- K2: per-class sums from bf16 (sorted order) --------------
// grid (4 dim-tiles, NC classes, 2), block 128
__global__ void __launch_bounds__(128) k_classsum(void) {
    int which = blockIdx.z;
    const __nv_bfloat16* __restrict__ z = g_z16[which];
    int k  = blockIdx.y;
    int p0 = blockIdx.x * 128;
    int t  = threadIdx.x;

    int s0 = g_start[k];
    int cnt = g_cnt[k];

    __shared__ int sidx[256];
    float acc = 0.0f;
    for (int base = 0; base < cnt; base += 256) {
        int m = cnt - base; if (m > 256) m = 256;
        __syncthreads();
        for (int i = t; i < m; i += 128) sidx[i] = g_order[s0 + base + i];
        __syncthreads();
        for (int i = 0; i < m; i++)
            acc += __bfloat162float(z[(size_t)sidx[i] * DD + p0 + t]);
    }
    g_clsraw[which][k * DD + p0 + t] = acc;
}

// ---------------- K3: Gram via wmma from row-major bf16 --------------------
// C[m][n] = sum_k Z[k][m] Z[k][n]; A col-major, B row-major, ld=136
// upper-triangle 128x128 tiles; grid (10, KSPLIT, 2), block 256 (8 warps 2x4)
__constant__ int c_mt[10] = {0,0,0,0,1,1,1,2,2,3};
__constant__ int c_nt[10] = {0,1,2,3,1,2,3,2,3,3};

#define GLD    136                      // bf16 elems per smem row (128 + 8 pad)
#define GROWB  (GLD * 2)                // 272 bytes
#define GBUF   (64 * GROWB)             // 17408 bytes per operand buffer
#define GT_SMEM (4 * GBUF)              // A0 B0 A1 B1 = 69632 bytes

__global__ void __launch_bounds__(256) k_gram(void) {
    extern __shared__ char smem[];
    const int which = blockIdx.z;
    const int tile = blockIdx.x;
    const __nv_bfloat16* __restrict__ src = g_z16[which];
    const int m0 = c_mt[tile] * 128;
    const int n0 = c_nt[tile] * 128;
    const int kbase = blockIdx.y * (NN / KSPLIT);   // 512 rows per block

    const uint32_t sb = smem_u32(smem);
    const int t = threadIdx.x;
    const int warpId = t >> 5;
    const int wm = warpId & 1;      // 2 warps in m (64 each)
    const int wn = warpId >> 1;     // 4 warps in n (32 each)

    wmma::fragment<wmma::accumulator, 16, 16, 16, float> acc[4][2];
#pragma unroll
    for (int i = 0; i < 4; i++)
#pragma unroll
        for (int j = 0; j < 2; j++) wmma::fill_fragment(acc[i][j], 0.0f);

    // stage chunk c (64 k-rows x 128 cols for A and B) into buffer c&1
    auto issue = [&](int c) {
        uint32_t abase = sb + (c & 1) * (2 * GBUF);
        uint32_t bbase = abase + GBUF;
        int k0 = kbase + c * 64;
        // 1024 vectors of 16B per operand; 256 threads -> 4 each
#pragma unroll
        for (int it = 0; it < 4; it++) {
            int idx = t + it * 256;
            int row = idx >> 4, kv = idx & 15;
            uint32_t off = row * GROWB + kv * 16;
            const __nv_bfloat16* gsrc = &src[(size_t)(k0 + row) * DD + kv * 8];
            cp16(abase + off, gsrc + m0);
            cp16(bbase + off, gsrc + n0);
        }
        asm volatile("cp.async.commit_group;" ::: "memory");
    };

    issue(0);
#pragma unroll 1
    for (int c = 0; c < 8; c++) {
        if (c + 1 < 8) {
            issue(c + 1);
            asm volatile("cp.async.wait_group 1;" ::: "memory");
        } else {
            asm volatile("cp.async.wait_group 0;" ::: "memory");
        }
        __syncthreads();

        const __nv_bfloat16* sA = (const __nv_bfloat16*)(smem + (c & 1) * (2 * GBUF));
        const __nv_bfloat16* sB = (const __nv_bfloat16*)(smem + (c & 1) * (2 * GBUF) + GBUF);
#pragma unroll
        for (int ks = 0; ks < 64; ks += 16) {
            wmma::fragment<wmma::matrix_a, 16, 16, 16, __nv_bfloat16, wmma::col_major> a_frag[4];
            wmma::fragment<wmma::matrix_b, 16, 16, 16, __nv_bfloat16, wmma::row_major> b_frag[2];
#pragma unroll
            for (int i = 0; i < 4; i++)
                wmma::load_matrix_sync(a_frag[i], sA + ks * GLD + wm * 64 + i * 16, GLD);
#pragma unroll
            for (int j = 0; j < 2; j++)
                wmma::load_matrix_sync(b_frag[j], sB + ks * GLD + wn * 32 + j * 16, GLD);
#pragma unroll
            for (int i = 0; i < 4; i++)
#pragma unroll
                for (int j = 0; j < 2; j++)
                    wmma::mma_sync(acc[i][j], a_frag[i], b_frag[j], acc[i][j]);
        }
        __syncthreads();
    }

    float* gp = g_gpart + (((size_t)which * KSPLIT + blockIdx.y) * 10 + tile) * 16384;
#pragma unroll
    for (int i = 0; i < 4; i++)
#pragma unroll
        for (int j = 0; j < 2; j++)
            wmma::store_matrix_sync(gp + (wm * 64 + i * 16) * 128 + wn * 32 + j * 16,
                                    acc[i][j], 128, wmma::mem_row_major);
}

// ---------------- K4: reductions (computes mu/is locally) ------------------
__global__ void __launch_bounds__(256) k_reduce(void) {
    __shared__ float s_mu[2][DD], s_is[2][DD];
    int t = threadIdx.x;
    for (int i = t; i < DD; i += 256) {
#pragma unroll
        for (int w = 0; w < 2; w++) {
            float mu  = g_colsum[w][i] * (1.0f / (float)NN);
            float var = (g_colsumsq[w][i] - (float)NN * mu * mu) * (1.0f / (float)(NN - 1));
            s_mu[w][i] = mu;
            s_is[w][i] = (float)(1.0 / sqrt((double)var));
        }
    }
    __syncthreads();

    int gid = blockIdx.x * 256 + t;
    const int GSZ = 128 * 256;

    double t1 = 0.0;
    for (int e = gid; e < 10 * 4096; e += GSZ) {
        int tile = e >> 12;
        int r = e & 4095;
        int i  = r >> 5;
        int j4 = (r & 31) << 2;
        int p  = c_mt[tile] * 128 + i;
        int qb = c_nt[tile] * 128 + j4;
        float w = (c_mt[tile] == c_nt[tile]) ? 1.0f : 2.0f;

        float4 ga = make_float4(0, 0, 0, 0), gb = make_float4(0, 0, 0, 0);
        size_t boff = (size_t)tile * 16384 + i * 128 + j4;
#pragma unroll
        for (int s = 0; s < KSPLIT; s++) {
            float4 va = *(const float4*)&g_gpart[((size_t)(0 * KSPLIT + s) * 10) * 16384 + boff];
            float4 vb = *(const float4*)&g_gpart[((size_t)(1 * KSPLIT + s) * 10) * 16384 + boff];
            ga.x += va.x; ga.y += va.y; ga.z += va.z; ga.w += va.w;
            gb.x += vb.x; gb.y += vb.y; gb.z += vb.z; gb.w += vb.w;
        }
        float4 qia = *(const float4*)&s_is[0][qb];
        float4 qma = *(const float4*)&s_mu[0][qb];
        float4 qib = *(const float4*)&s_is[1][qb];
        float4 qmb = *(const float4*)&s_mu[1][qb];
        float pia = s_is[0][p], pma = s_mu[0][p], pib = s_is[1][p], pmb = s_mu[1][p];

        float ax = pia * qia.x * (ga.x - (float)NN * pma * qma.x);
        float ay = pia * qia.y * (ga.y - (float)NN * pma * qma.y);
        float az = pia * qia.z * (ga.z - (float)NN * pma * qma.z);
        float aw = pia * qia.w * (ga.w - (float)NN * pma * qma.w);
        float bx = pib * qib.x * (gb.x - (float)NN * pmb * qmb.x);
        float by = pib * qib.y * (gb.y - (float)NN * pmb * qmb.y);
        float bz = pib * qib.z * (gb.z - (float)NN * pmb * qmb.z);
        float bw = pib * qib.w * (gb.w - (float)NN * pmb * qmb.w);
        t1 += (double)(w * (ax * bx + ay * by + az * bz + aw * bw));
    }

    double cr = 0.0;
    for (int idx = gid; idx < NC * DD; idx += GSZ) {
        int k = idx >> 9, p = idx & (DD - 1);
        float nk = (float)g_cnt[k];
        float u = s_is[0][p] * (g_clsraw[0][idx] - nk * s_mu[0][p]);
        float v = s_is[1][p] * (g_clsraw[1][idx] - nk * s_mu[1][p]);
        cr += (double)(u * v);
    }

    __shared__ double st1[256], scr[256];
    st1[t] = t1; scr[t] = cr;
    __syncthreads();
    for (int s = 128; s > 0; s >>= 1) {
        if (t < s) { st1[t] += st1[t + s]; scr[t] += scr[t + s]; }
        __syncthreads();
    }
    if (t == 0) {
        atomicAdd(&g_acc[0], st1[0]);
        atomicAdd(&g_acc[1], scr[0]);
    }
}

// ---------------- K5: finalize ---------------------------------------------
__global__ void k_final(float* __restrict__ out) {
    double m2 = 0.0;
    for (int k = 0; k < NC; k++) {
        double n = (double)g_cnt[k];
        m2 += n * n;
    }
    double loss = g_acc[0] / ((double)DD * (double)DD)
                - 2.0 * g_acc[1] / (double)DD
                + m2;
    out[0] = (float)loss;
}

// ---------------- launch ----------------------------------------------------
extern "C" void kernel_launch(void* const* d_in, const int* in_sizes, int n_in,
                              void* d_out, int out_size) {
    const float* za = (const float*)d_in[0];
    const float* zb = (const float*)d_in[1];
    const int* labels = (const int*)d_in[2];
    float* out = (float*)d_out;

    static int smem_set = 0;
    if (!smem_set) {
        cudaFuncSetAttribute(k_gram, cudaFuncAttributeMaxDynamicSharedMemorySize, GT_SMEM);
        smem_set = 1;
    }

    k_prep<<<1, 1024>>>(labels);
    { dim3 g(4, 32, 2); k_convert<<<g, 256>>>(za, zb); }
    { dim3 g(4, NC, 2); k_classsum<<<g, 128>>>(); }
    { dim3 g(10, KSPLIT, 2); k_gram<<<g, 256, GT_SMEM>>>(); }
    k_reduce<<<128, 256>>>();
    k_final<<<1, 1>>>(out);
}